// round 2
// baseline (speedup 1.0000x reference)
#include <cuda_runtime.h>
#include <math.h>

#define NSEQ   400
#define SLEN   301
#define DMOD   64
#define NHEAD  8
#define HDIM   8
#define FFD    256
#define NTOK   (NSEQ*SLEN)   /* 120400 */
#define TT     16
#define NBLK   (NTOK/TT)     /* 7525 */
#define EPSF   1e-5f

/* scratch (device globals: allocation-free, graph-safe) */
__device__ float g_h [NTOK*DMOD];
__device__ float g_q [NTOK*DMOD];
__device__ float g_k [NTOK*DMOD];
__device__ float g_v [NTOK*DMOD];
__device__ float g_ao[NTOK*DMOD];
__device__ float g_ff[NTOK*FFD];

__device__ __forceinline__ float warp_sum(float v) {
#pragma unroll
    for (int o = 16; o; o >>= 1) v += __shfl_xor_sync(0xffffffffu, v, o);
    return v;
}

__device__ __forceinline__ float gelu_exact(float x) {
    return 0.5f * x * (1.0f + erff(x * 0.7071067811865476f));
}

/* ------------------------------------------------------------------ */
/* embed: h[n,s,:] = LN(x@We.T + be) (+cls at s=0) + pos_encoding      */
__global__ void embed_kernel(const float* __restrict__ x,
                             const float* __restrict__ ew,
                             const float* __restrict__ eb,
                             const float* __restrict__ gg,
                             const float* __restrict__ gb,
                             const float* __restrict__ cls) {
    int tok = blockIdx.x;
    int n = tok / SLEN, s = tok - n * SLEN;
    int d = threadIdx.x;
    __shared__ float r1[64], r2[64];
    __shared__ float sh_mu, sh_rs;

    float val;
    if (s == 0) {
        val = cls[d];
    } else {
        int b = n / 25, e = n - b * 25;
        int t = s - 1;
        const float* xp = x + ((size_t)b * 3 * 300 + t) * 25 + e; /* x[b][c][t][e] */
        float acc = eb[d];
        acc += ew[d * 3 + 0] * xp[0];
        acc += ew[d * 3 + 1] * xp[300 * 25];
        acc += ew[d * 3 + 2] * xp[2 * 300 * 25];
        r1[d] = acc; r2[d] = acc * acc;
        __syncthreads();
        if (d < 32) {
            float s1 = warp_sum(r1[d] + r1[d + 32]);
            float s2 = warp_sum(r2[d] + r2[d + 32]);
            if (d == 0) {
                float mu = s1 * (1.0f / 64.0f);
                sh_mu = mu;
                sh_rs = rsqrtf(s2 * (1.0f / 64.0f) - mu * mu + EPSF);
            }
        }
        __syncthreads();
        val = (acc - sh_mu) * sh_rs * gg[d] + gb[d];
    }
    /* positional encoding */
    int i2 = d & ~1;
    float freq = expf(-0.14391156831212787f * (float)i2); /* ln(1e4)/64 */
    float ang = (float)s * freq;
    val += (d & 1) ? cosf(ang) : sinf(ang);
    g_h[(size_t)tok * 64 + d] = val;
}

/* ------------------------------------------------------------------ */
/* LN1 + QKV projection, scatter to [n,h,s,hd] layout                  */
__global__ void ln_qkv_kernel(const float* __restrict__ w,
                              const float* __restrict__ bias,
                              const float* __restrict__ lg,
                              const float* __restrict__ lb) {
    extern __shared__ float sm[];
    float* ws = sm;              /* 64 x 193 (transposed, padded) */
    float* sy = sm + 64 * 193;   /* 16 x 64 LN'd activations */
    int tid = threadIdx.x;
    int tok0 = blockIdx.x * TT;

    for (int p = tid; p < 192 * 64; p += 256)
        ws[(p & 63) * 193 + (p >> 6)] = w[p];

    int warp = tid >> 5, lane = tid & 31;
    float gl0 = lg[lane], gl1 = lg[lane + 32];
    float bl0 = lb[lane], bl1 = lb[lane + 32];
#pragma unroll
    for (int r = 0; r < 2; r++) {
        int t = warp * 2 + r;
        const float* hp = g_h + (size_t)(tok0 + t) * 64;
        float v0 = hp[lane], v1 = hp[lane + 32];
        float s1 = warp_sum(v0 + v1);
        float s2 = warp_sum(v0 * v0 + v1 * v1);
        float mu = s1 * (1.0f / 64.0f);
        float rs = rsqrtf(s2 * (1.0f / 64.0f) - mu * mu + EPSF);
        sy[t * 64 + lane]      = (v0 - mu) * rs * gl0 + bl0;
        sy[t * 64 + lane + 32] = (v1 - mu) * rs * gl1 + bl1;
    }
    __syncthreads();

    int ox = tid & 63, ty = tid >> 6;
    float a0[4] = {0,0,0,0}, a1[4] = {0,0,0,0}, a2[4] = {0,0,0,0};
#pragma unroll 4
    for (int k = 0; k < 64; k++) {
        float w0 = ws[k * 193 + ox];
        float w1 = ws[k * 193 + ox + 64];
        float w2 = ws[k * 193 + ox + 128];
#pragma unroll
        for (int j = 0; j < 4; j++) {
            float yv = sy[(ty + 4 * j) * 64 + k];
            a0[j] += yv * w0; a1[j] += yv * w1; a2[j] += yv * w2;
        }
    }
    float b0 = bias[ox], b1 = bias[ox + 64], b2 = bias[ox + 128];
    int head = ox >> 3, hd = ox & 7;
#pragma unroll
    for (int j = 0; j < 4; j++) {
        int tok = tok0 + ty + 4 * j;
        int n = tok / SLEN, s = tok - n * SLEN;
        int base = ((n * 8 + head) * SLEN + s) * 8 + hd;
        g_q[base] = a0[j] + b0;
        g_k[base] = a1[j] + b1;
        g_v[base] = a2[j] + b2;
    }
}

/* ------------------------------------------------------------------ */
/* fused attention: one block per (seq, head), flash-style             */
__global__ void attn_kernel() {
    __shared__ float sk[SLEN * 8];
    __shared__ float sv[SLEN * 8];
    int nh = blockIdx.x;
    const float* kb = g_k + (size_t)nh * SLEN * 8;
    const float* vb = g_v + (size_t)nh * SLEN * 8;
    for (int i = threadIdx.x; i < SLEN * 8; i += 320) { sk[i] = kb[i]; sv[i] = vb[i]; }
    __syncthreads();
    int sq = threadIdx.x;
    if (sq >= SLEN) return;

    const float4* qp = (const float4*)(g_q + ((size_t)nh * SLEN + sq) * 8);
    float4 q0 = qp[0], q1 = qp[1];
    const float SC = 0.35355339059327373f; /* 1/sqrt(8) */
    float l = 0.0f;
    float a0=0,a1=0,a2=0,a3=0,a4=0,a5=0,a6=0,a7=0;
    for (int j = 0; j < SLEN; j++) {
        float4 k0 = *(const float4*)(sk + j * 8);
        float4 k1 = *(const float4*)(sk + j * 8 + 4);
        float s = q0.x*k0.x + q0.y*k0.y + q0.z*k0.z + q0.w*k0.w
                + q1.x*k1.x + q1.y*k1.y + q1.z*k1.z + q1.w*k1.w;
        float p = __expf(s * SC);   /* scores |s|<<1: no max-sub needed */
        l += p;
        float4 v0 = *(const float4*)(sv + j * 8);
        float4 v1 = *(const float4*)(sv + j * 8 + 4);
        a0 += p*v0.x; a1 += p*v0.y; a2 += p*v0.z; a3 += p*v0.w;
        a4 += p*v1.x; a5 += p*v1.y; a6 += p*v1.z; a7 += p*v1.w;
    }
    float inv = 1.0f / l;
    int n = nh >> 3, h = nh & 7;
    float* op = g_ao + ((size_t)n * SLEN + sq) * 64 + h * 8;
    *(float4*)op       = make_float4(a0*inv, a1*inv, a2*inv, a3*inv);
    *(float4*)(op + 4) = make_float4(a4*inv, a5*inv, a6*inv, a7*inv);
}

/* ------------------------------------------------------------------ */
/* out-projection + residual: h += ao @ Wo.T + bo                      */
__global__ void outproj_kernel(const float* __restrict__ w,
                               const float* __restrict__ bias) {
    extern __shared__ float sm[];
    float* ws = sm;            /* 64 x 65 */
    float* sy = sm + 64 * 65;  /* 16 x 64 */
    int tid = threadIdx.x;
    int tok0 = blockIdx.x * TT;
    for (int p = tid; p < 64 * 64; p += 256)
        ws[(p & 63) * 65 + (p >> 6)] = w[p];
    for (int i = tid; i < TT * 64; i += 256)
        sy[i] = g_ao[(size_t)tok0 * 64 + i];
    __syncthreads();
    int ox = tid & 63, ty = tid >> 6;
    float a[4] = {0,0,0,0};
#pragma unroll 4
    for (int k = 0; k < 64; k++) {
        float wv = ws[k * 65 + ox];
#pragma unroll
        for (int j = 0; j < 4; j++) a[j] += sy[(ty + 4 * j) * 64 + k] * wv;
    }
    float bo = bias[ox];
#pragma unroll
    for (int j = 0; j < 4; j++)
        g_h[(size_t)(tok0 + ty + 4 * j) * 64 + ox] += a[j] + bo;
}

/* ------------------------------------------------------------------ */
/* LN2 + FF1 + exact GELU -> g_ff                                      */
__global__ void ln_ff1_kernel(const float* __restrict__ w,
                              const float* __restrict__ bias,
                              const float* __restrict__ lg,
                              const float* __restrict__ lb) {
    extern __shared__ float sm[];
    float* ws = sm;              /* 64 x 257 */
    float* sy = sm + 64 * 257;   /* 16 x 64 */
    int tid = threadIdx.x;
    int tok0 = blockIdx.x * TT;
    for (int p = tid; p < 256 * 64; p += 256)
        ws[(p & 63) * 257 + (p >> 6)] = w[p];

    int warp = tid >> 5, lane = tid & 31;
    float gl0 = lg[lane], gl1 = lg[lane + 32];
    float bl0 = lb[lane], bl1 = lb[lane + 32];
#pragma unroll
    for (int r = 0; r < 2; r++) {
        int t = warp * 2 + r;
        const float* hp = g_h + (size_t)(tok0 + t) * 64;
        float v0 = hp[lane], v1 = hp[lane + 32];
        float s1 = warp_sum(v0 + v1);
        float s2 = warp_sum(v0 * v0 + v1 * v1);
        float mu = s1 * (1.0f / 64.0f);
        float rs = rsqrtf(s2 * (1.0f / 64.0f) - mu * mu + EPSF);
        sy[t * 64 + lane]      = (v0 - mu) * rs * gl0 + bl0;
        sy[t * 64 + lane + 32] = (v1 - mu) * rs * gl1 + bl1;
    }
    __syncthreads();

    int ox = tid & 63, ty = tid >> 6;
    float a0[4] = {0,0,0,0}, a1[4] = {0,0,0,0}, a2[4] = {0,0,0,0}, a3[4] = {0,0,0,0};
#pragma unroll 4
    for (int k = 0; k < 64; k++) {
        float w0 = ws[k * 257 + ox];
        float w1 = ws[k * 257 + ox + 64];
        float w2 = ws[k * 257 + ox + 128];
        float w3 = ws[k * 257 + ox + 192];
#pragma unroll
        for (int j = 0; j < 4; j++) {
            float yv = sy[(ty + 4 * j) * 64 + k];
            a0[j] += yv * w0; a1[j] += yv * w1; a2[j] += yv * w2; a3[j] += yv * w3;
        }
    }
    float b0 = bias[ox], b1 = bias[ox + 64], b2 = bias[ox + 128], b3 = bias[ox + 192];
#pragma unroll
    for (int j = 0; j < 4; j++) {
        size_t base = (size_t)(tok0 + ty + 4 * j) * 256;
        g_ff[base + ox]       = gelu_exact(a0[j] + b0);
        g_ff[base + ox + 64]  = gelu_exact(a1[j] + b1);
        g_ff[base + ox + 128] = gelu_exact(a2[j] + b2);
        g_ff[base + ox + 192] = gelu_exact(a3[j] + b3);
    }
}

/* ------------------------------------------------------------------ */
/* FF2 + residual: h += g_ff @ W2.T + b2                               */
__global__ void ff2_kernel(const float* __restrict__ w,
                           const float* __restrict__ bias) {
    extern __shared__ float sm[];
    float* ws = sm;              /* 256 x 65 */
    float* sy = sm + 256 * 65;   /* 16 x 256 */
    int tid = threadIdx.x;
    int tok0 = blockIdx.x * TT;
    for (int p = tid; p < 64 * 256; p += 256)
        ws[(p & 255) * 65 + (p >> 8)] = w[p];
    for (int i = tid; i < TT * 256; i += 256)
        sy[i] = g_ff[(size_t)tok0 * 256 + i];
    __syncthreads();
    int ox = tid & 63, ty = tid >> 6;
    float a[4] = {0,0,0,0};
#pragma unroll 4
    for (int k = 0; k < 256; k++) {
        float wv = ws[k * 65 + ox];
#pragma unroll
        for (int j = 0; j < 4; j++) a[j] += sy[(ty + 4 * j) * 256 + k] * wv;
    }
    float bo = bias[ox];
#pragma unroll
    for (int j = 0; j < 4; j++)
        g_h[(size_t)(tok0 + ty + 4 * j) * 64 + ox] += a[j] + bo;
}

/* ------------------------------------------------------------------ */
/* head: cls-pool mean over E, LN, GELU(h1), h2 -> out [16,60]         */
__global__ void head_kernel(const float* __restrict__ ng, const float* __restrict__ nb,
                            const float* __restrict__ h1w, const float* __restrict__ h1b,
                            const float* __restrict__ h2w, const float* __restrict__ h2b,
                            float* __restrict__ out) {
    int b = blockIdx.x, d = threadIdx.x;
    __shared__ float r1[64], r2[64], fy[64], g1[64];
    __shared__ float sh_mu, sh_rs;
    float acc = 0.0f;
    for (int e = 0; e < 25; e++)
        acc += g_h[(size_t)((b * 25 + e) * SLEN) * 64 + d];
    acc *= (1.0f / 25.0f);
    r1[d] = acc; r2[d] = acc * acc;
    __syncthreads();
    if (d < 32) {
        float s1 = warp_sum(r1[d] + r1[d + 32]);
        float s2 = warp_sum(r2[d] + r2[d + 32]);
        if (d == 0) {
            float mu = s1 * (1.0f / 64.0f);
            sh_mu = mu;
            sh_rs = rsqrtf(s2 * (1.0f / 64.0f) - mu * mu + EPSF);
        }
    }
    __syncthreads();
    fy[d] = (acc - sh_mu) * sh_rs * ng[d] + nb[d];
    __syncthreads();
    float a1 = h1b[d];
    for (int k = 0; k < 64; k++) a1 += fy[k] * h1w[d * 64 + k];
    g1[d] = gelu_exact(a1);
    __syncthreads();
    if (d < 60) {
        float a2 = h2b[d];
        for (int k = 0; k < 64; k++) a2 += g1[k] * h2w[d * 64 + k];
        out[b * 60 + d] = a2;
    }
}

/* ------------------------------------------------------------------ */
extern "C" void kernel_launch(void* const* d_in, const int* in_sizes, int n_in,
                              void* d_out, int out_size) {
    const float* x     = (const float*)d_in[0];
    const float* ew    = (const float*)d_in[1];
    const float* eb    = (const float*)d_in[2];
    const float* elng  = (const float*)d_in[3];
    const float* elnb  = (const float*)d_in[4];
    const float* cls   = (const float*)d_in[5];
    const float* qkvw  = (const float*)d_in[6];
    const float* qkvb  = (const float*)d_in[7];
    const float* outw  = (const float*)d_in[8];
    const float* outb  = (const float*)d_in[9];
    const float* ln1g  = (const float*)d_in[10];
    const float* ln1b  = (const float*)d_in[11];
    const float* ln2g  = (const float*)d_in[12];
    const float* ln2b  = (const float*)d_in[13];
    const float* ff1w  = (const float*)d_in[14];
    const float* ff1b  = (const float*)d_in[15];
    const float* ff2w  = (const float*)d_in[16];
    const float* ff2b  = (const float*)d_in[17];
    const float* normg = (const float*)d_in[18];
    const float* normb = (const float*)d_in[19];
    const float* h1w   = (const float*)d_in[20];
    const float* h1b   = (const float*)d_in[21];
    const float* h2w   = (const float*)d_in[22];
    const float* h2b   = (const float*)d_in[23];
    float* out = (float*)d_out;

    cudaFuncSetAttribute(ln_qkv_kernel, cudaFuncAttributeMaxDynamicSharedMemorySize, 56 * 1024);
    cudaFuncSetAttribute(ln_ff1_kernel, cudaFuncAttributeMaxDynamicSharedMemorySize, 72 * 1024);
    cudaFuncSetAttribute(ff2_kernel,    cudaFuncAttributeMaxDynamicSharedMemorySize, 88 * 1024);

    embed_kernel<<<NTOK, 64>>>(x, ew, eb, elng, elnb, cls);
    for (int l = 0; l < 4; l++) {
        ln_qkv_kernel<<<NBLK, 256, (64 * 193 + TT * 64) * 4>>>(
            qkvw + l * 192 * 64, qkvb + l * 192, ln1g + l * 64, ln1b + l * 64);
        attn_kernel<<<NSEQ * NHEAD, 320>>>();
        outproj_kernel<<<NBLK, 256, (64 * 65 + TT * 64) * 4>>>(
            outw + l * 64 * 64, outb + l * 64);
        ln_ff1_kernel<<<NBLK, 256, (64 * 257 + TT * 64) * 4>>>(
            ff1w + l * 256 * 64, ff1b + l * 256, ln2g + l * 64, ln2b + l * 64);
        ff2_kernel<<<NBLK, 256, (256 * 65 + TT * 256) * 4>>>(
            ff2w + l * 64 * 256, ff2b + l * 64);
    }
    head_kernel<<<16, 64>>>(normg, normb, h1w, h1b, h2w, h2b, out);
}